// round 16
// baseline (speedup 1.0000x reference)
#include <cuda_runtime.h>
#include <cuda_bf16.h>
#include <cuda_fp16.h>

#define N_MAX 100000
#define NF 128
#define NH 64
#define NC 16

// Scratch (alloc-free rule: __device__ globals)
__device__ __half g_h0h[N_MAX * NH];   // x @ W1, fp16
__device__ float  g_h1[N_MAX * NH];    // layer-1 aggregate, fp32
__device__ __half g_h2h[N_MAX * NC];   // relu(h1) @ W2, fp16

// ---------------- bit-cast helpers -----------------------------------------
__device__ __forceinline__ unsigned int h2_to_u(__half2 h) {
    unsigned int u; memcpy(&u, &h, 4); return u;
}
__device__ __forceinline__ __half2 u_to_h2(unsigned int u) {
    __half2 h; memcpy(&h, &u, 4); return h;
}

// ---------------- packed f32x2 helpers -------------------------------------
__device__ __forceinline__ unsigned long long pk2(float lo, float hi) {
    unsigned long long r;
    asm("mov.b64 %0, {%1, %2};" : "=l"(r) : "f"(lo), "f"(hi));
    return r;
}
__device__ __forceinline__ void fma2(unsigned long long& d,
                                     unsigned long long a, unsigned long long b) {
    asm("fma.rn.f32x2 %0, %1, %2, %0;" : "+l"(d) : "l"(a), "l"(b));
}
__device__ __forceinline__ float2 upk2(unsigned long long v) {
    float2 f;
    asm("mov.b64 {%0, %1}, %2;" : "=f"(f.x), "=f"(f.y) : "l"(v));
    return f;
}

// ---------------------------------------------------------------------------
// GEMM1: h0 = x @ W1 (fp32 math, FFMA2), stored fp16. Zeroes g_h1 rows.
// ---------------------------------------------------------------------------
__global__ void __launch_bounds__(256) gemm1_kernel(
    const float* __restrict__ x, const float* __restrict__ W1, int n)
{
    __shared__ float ws[NF * NH];    // [k][c], 32 KB
    __shared__ float xs[32 * 68];    // [k_local][row]

    int tid = threadIdx.x;
    #pragma unroll
    for (int i = tid; i < NF * NH / 4; i += 256)
        ((float4*)ws)[i] = ((const float4*)W1)[i];

    int row0 = blockIdx.x * 64;
    int tx = tid & 15, ty = tid >> 4;
    int r0 = ty * 4, c0 = tx * 4;
    int kq = tid & 7;
    int lrow = tid >> 3;

    unsigned long long acc[2][4] = {};   // [rowpair][col]

    for (int kc = 0; kc < 4; kc++) {
        __syncthreads();
        #pragma unroll
        for (int pass = 0; pass < 2; pass++) {
            int row = lrow + pass * 32;
            int grow = row0 + row;
            float4 v = make_float4(0.f, 0.f, 0.f, 0.f);
            if (grow < n)
                v = *(const float4*)&x[grow * NF + kc * 32 + kq * 4];
            xs[(kq * 4 + 0) * 68 + row] = v.x;
            xs[(kq * 4 + 1) * 68 + row] = v.y;
            xs[(kq * 4 + 2) * 68 + row] = v.z;
            xs[(kq * 4 + 3) * 68 + row] = v.w;
        }
        __syncthreads();
        #pragma unroll
        for (int kk = 0; kk < 32; kk++) {
            float4 b = *(const float4*)&ws[(kc * 32 + kk) * NH + c0];
            float4 a = *(const float4*)&xs[kk * 68 + r0];
            unsigned long long a01 = pk2(a.x, a.y);
            unsigned long long a23 = pk2(a.z, a.w);
            unsigned long long b0 = pk2(b.x, b.x);
            unsigned long long b1 = pk2(b.y, b.y);
            unsigned long long b2 = pk2(b.z, b.z);
            unsigned long long b3 = pk2(b.w, b.w);
            fma2(acc[0][0], a01, b0); fma2(acc[1][0], a23, b0);
            fma2(acc[0][1], a01, b1); fma2(acc[1][1], a23, b1);
            fma2(acc[0][2], a01, b2); fma2(acc[1][2], a23, b2);
            fma2(acc[0][3], a01, b3); fma2(acc[1][3], a23, b3);
        }
    }

    #pragma unroll
    for (int rp = 0; rp < 2; rp++) {
        float2 c0v = upk2(acc[rp][0]);
        float2 c1v = upk2(acc[rp][1]);
        float2 c2v = upk2(acc[rp][2]);
        float2 c3v = upk2(acc[rp][3]);
        int gr0 = row0 + r0 + 2 * rp;
        if (gr0 < n) {
            __half2 h01 = __floats2half2_rn(c0v.x, c1v.x);
            __half2 h23 = __floats2half2_rn(c2v.x, c3v.x);
            *(uint2*)&g_h0h[gr0 * NH + c0] = make_uint2(h2_to_u(h01), h2_to_u(h23));
            *(float4*)&g_h1[gr0 * NH + c0] = make_float4(0.f, 0.f, 0.f, 0.f);
        }
        if (gr0 + 1 < n) {
            __half2 h01 = __floats2half2_rn(c0v.y, c1v.y);
            __half2 h23 = __floats2half2_rn(c2v.y, c3v.y);
            *(uint2*)&g_h0h[(gr0 + 1) * NH + c0] = make_uint2(h2_to_u(h01), h2_to_u(h23));
            *(float4*)&g_h1[(gr0 + 1) * NH + c0] = make_float4(0.f, 0.f, 0.f, 0.f);
        }
    }
}

// ---------------------------------------------------------------------------
// Scatter1: g_h1[dst] += h0h[src] * w.
// NEW geometry: 128 edges/block, 8 lanes/edge, 4 edges/thread.
// Lane: 1 LDG.128 (8 fp16) + 2 RED.v4.f32  -> 24 LSU lanes/edge (was 32).
// __launch_bounds__(256,7) caps regs ~36 to protect occupancy.
// ---------------------------------------------------------------------------
__global__ void __launch_bounds__(256, 7) scatter1_kernel(
    const int* __restrict__ ei, const float* __restrict__ ew, int E)
{
    __shared__ int   ssrc[128];
    __shared__ int   sdst[128];
    __shared__ float sw[128];

    int tid = threadIdx.x;
    int ebase = blockIdx.x * 128;
    if (tid < 128) {
        int e = ebase + tid;
        ssrc[tid] = (e < E) ? __ldg(&ei[e]) : -1;
        sw[tid]   = (e < E) ? __ldg(&ew[e]) : 0.f;
    } else {
        int e = ebase + (tid - 128);
        sdst[tid - 128] = (e < E) ? __ldg(&ei[E + e]) : 0;
    }
    __syncthreads();

    int g = tid >> 3;          // edge-slot 0..31
    int q = tid & 7;           // 8-half chunk 0..7

    int   s[4], d[4];
    float w[4];
    uint4 raw[4];

    #pragma unroll
    for (int u = 0; u < 4; u++) {
        int le = g + u * 32;
        s[u] = ssrc[le];
        d[u] = sdst[le];
        w[u] = sw[le];
    }
    #pragma unroll
    for (int u = 0; u < 4; u++) {
        raw[u] = make_uint4(0, 0, 0, 0);
        if (s[u] >= 0)
            raw[u] = __ldg((const uint4*)(g_h0h + s[u] * NH + q * 8));
    }
    #pragma unroll
    for (int u = 0; u < 4; u++) {
        if (s[u] < 0) continue;
        float wt = w[u];
        float2 f0 = __half22float2(u_to_h2(raw[u].x));
        float2 f1 = __half22float2(u_to_h2(raw[u].y));
        float2 f2 = __half22float2(u_to_h2(raw[u].z));
        float2 f3 = __half22float2(u_to_h2(raw[u].w));
        float* base = &g_h1[d[u] * NH + q * 8];
        asm volatile("red.global.add.v4.f32 [%0], {%1,%2,%3,%4};"
                     :: "l"(base),
                        "f"(f0.x * wt), "f"(f0.y * wt),
                        "f"(f1.x * wt), "f"(f1.y * wt)
                     : "memory");
        asm volatile("red.global.add.v4.f32 [%0], {%1,%2,%3,%4};"
                     :: "l"(base + 4),
                        "f"(f2.x * wt), "f"(f2.y * wt),
                        "f"(f3.x * wt), "f"(f3.y * wt)
                     : "memory");
    }
}

// ---------------------------------------------------------------------------
// GEMM2: h2 = relu(h1) @ W2 (fp32 math), stored fp16; zeroes d_out rows.
// ---------------------------------------------------------------------------
__global__ void __launch_bounds__(256) gemm2_kernel(
    const float* __restrict__ W2, float* __restrict__ out, int n)
{
    __shared__ float ws[NH * NC];
    __shared__ float hs[64 * 65];

    int tid = threadIdx.x;
    #pragma unroll
    for (int i = tid; i < NH * NC / 4; i += 256)
        ((float4*)ws)[i] = ((const float4*)W2)[i];

    int row0 = blockIdx.x * 64;
    #pragma unroll
    for (int idx = tid; idx < 64 * 64; idx += 256) {
        int r = idx >> 6, k = idx & 63;
        int grow = row0 + r;
        float v = 0.f;
        if (grow < n) v = g_h1[grow * NH + k];
        hs[r * 65 + k] = fmaxf(v, 0.f);   // fused ReLU
    }
    __syncthreads();

    int cg = tid & 3, r = tid >> 2;
    float a0 = 0.f, a1 = 0.f, a2 = 0.f, a3 = 0.f;
    #pragma unroll
    for (int k = 0; k < NH; k++) {
        float a = hs[r * 65 + k];
        float4 b = *(const float4*)&ws[k * NC + cg * 4];
        a0 += a * b.x; a1 += a * b.y; a2 += a * b.z; a3 += a * b.w;
    }

    int grow = row0 + r;
    if (grow < n) {
        __half2 h01 = __floats2half2_rn(a0, a1);
        __half2 h23 = __floats2half2_rn(a2, a3);
        *(uint2*)&g_h2h[grow * NC + cg * 4] = make_uint2(h2_to_u(h01), h2_to_u(h23));
        *(float4*)&out[grow * NC + cg * 4]  = make_float4(0.f, 0.f, 0.f, 0.f);
    }
}

// ---------------------------------------------------------------------------
// Scatter2: out[dst] += h2h[src] * w.  UNCHANGED from R14 (27.3us config):
// 256 edges/block, 4 lanes/edge, 4 edges/thread, LDG.64 fp16 + 1 RED.v4.
// ---------------------------------------------------------------------------
__global__ void __launch_bounds__(256) scatter2_kernel(
    const int* __restrict__ ei, const float* __restrict__ ew,
    float* __restrict__ out, int E)
{
    __shared__ int   ssrc[256];
    __shared__ int   sdst[256];
    __shared__ float sw[256];

    int tid = threadIdx.x;
    int ebase = blockIdx.x * 256;
    {
        int e = ebase + tid;
        ssrc[tid] = (e < E) ? __ldg(&ei[e]) : -1;
        sdst[tid] = (e < E) ? __ldg(&ei[E + e]) : 0;
        sw[tid]   = (e < E) ? __ldg(&ew[e]) : 0.f;
    }
    __syncthreads();

    int g = tid >> 2;          // edge-slot 0..63
    int q = tid & 3;           // feature quad 0..3

    int   s[4], d[4];
    float w[4];
    uint2 raw[4];

    #pragma unroll
    for (int u = 0; u < 4; u++) {
        int le = g + u * 64;
        s[u] = ssrc[le];
        d[u] = sdst[le];
        w[u] = sw[le];
    }
    #pragma unroll
    for (int u = 0; u < 4; u++) {
        raw[u] = make_uint2(0, 0);
        if (s[u] >= 0)
            raw[u] = __ldg((const uint2*)(g_h2h + s[u] * NC + q * 4));
    }
    #pragma unroll
    for (int u = 0; u < 4; u++) {
        if (s[u] >= 0) {
            float wt = w[u];
            float2 f0 = __half22float2(u_to_h2(raw[u].x));
            float2 f1 = __half22float2(u_to_h2(raw[u].y));
            asm volatile("red.global.add.v4.f32 [%0], {%1,%2,%3,%4};"
                         :: "l"(&out[d[u] * NC + q * 4]),
                            "f"(f0.x * wt), "f"(f0.y * wt),
                            "f"(f1.x * wt), "f"(f1.y * wt)
                         : "memory");
        }
    }
}

// ---------------------------------------------------------------------------
extern "C" void kernel_launch(void* const* d_in, const int* in_sizes, int n_in,
                              void* d_out, int out_size)
{
    const float* x   = (const float*)d_in[0];
    const int*   ei1 = (const int*)  d_in[1];
    const int*   ei2 = (const int*)  d_in[2];
    const float* ew1 = (const float*)d_in[3];
    const float* ew2 = (const float*)d_in[4];
    const float* W1  = (const float*)d_in[5];
    const float* W2  = (const float*)d_in[6];
    float* out = (float*)d_out;

    int n  = in_sizes[0] / NF;
    int E1 = in_sizes[3];
    int E2 = in_sizes[4];
    int nb = (n + 63) / 64;

    gemm1_kernel<<<nb, 256>>>(x, W1, n);                       // writes h0h, zeroes g_h1
    scatter1_kernel<<<(E1 + 127) / 128, 256>>>(ei1, ew1, E1);
    gemm2_kernel<<<nb, 256>>>(W2, out, n);                     // writes h2h, zeroes out
    scatter2_kernel<<<(E2 + 255) / 256, 256>>>(ei2, ew2, out, E2);
}

// round 17
// speedup vs baseline: 1.4462x; 1.4462x over previous
#include <cuda_runtime.h>
#include <cuda_bf16.h>
#include <cuda_fp16.h>
#include <mma.h>

using namespace nvcuda;

#define N_MAX 100000
#define NF 128
#define NH 64
#define NC 16

// Scratch (alloc-free rule: __device__ globals)
__device__ __half g_h0h[N_MAX * NH];   // x @ W1, fp16
__device__ float  g_h1[N_MAX * NH];    // layer-1 aggregate, fp32
__device__ __half g_h2h[N_MAX * NC];   // relu(h1) @ W2, fp16

// ---------------- bit-cast helpers -----------------------------------------
__device__ __forceinline__ unsigned int h2_to_u(__half2 h) {
    unsigned int u; memcpy(&u, &h, 4); return u;
}
__device__ __forceinline__ __half2 u_to_h2(unsigned int u) {
    __half2 h; memcpy(&h, &u, 4); return h;
}

// ---------------------------------------------------------------------------
// GEMM1 (tensor core): h0[64-row tile] = x_tile(fp16) @ W1(fp16), fp32 accum.
// fp32->fp16 conversion happens in the smem staging path. Stores h0h fp16 and
// zeroes this block's g_h1 rows. Block 256 (8 warps), tile 64x64, K=128.
// Warp w: m-tile = w>>1 (16 rows), n-tiles = (w&1)*2 .. +1 (2x16 cols).
// ---------------------------------------------------------------------------
__global__ void __launch_bounds__(256) gemm1_kernel(
    const float* __restrict__ x, const float* __restrict__ W1, int n)
{
    __shared__ __half Ah[64 * 136];    // x tile, fp16, ldm 136 (17408 B)
    __shared__ __half Bh[128 * 72];    // W1, fp16, ldm 72 (18432 B)

    int tid = threadIdx.x;
    int row0 = blockIdx.x * 64;

    // W1 fp32 -> Bh fp16 (128x64)
    #pragma unroll
    for (int i = tid; i < 128 * 16; i += 256) {
        int r = i >> 4, c4 = i & 15;
        float4 v = *(const float4*)&W1[r * NH + c4 * 4];
        __half2 h01 = __floats2half2_rn(v.x, v.y);
        __half2 h23 = __floats2half2_rn(v.z, v.w);
        *(uint2*)&Bh[r * 72 + c4 * 4] = make_uint2(h2_to_u(h01), h2_to_u(h23));
    }

    // x rows fp32 -> Ah fp16 (64x128), zero-pad rows >= n
    #pragma unroll
    for (int i = tid; i < 64 * 32; i += 256) {
        int r = i >> 5, c4 = i & 31;
        int grow = row0 + r;
        float4 v = make_float4(0.f, 0.f, 0.f, 0.f);
        if (grow < n) v = *(const float4*)&x[grow * NF + c4 * 4];
        __half2 h01 = __floats2half2_rn(v.x, v.y);
        __half2 h23 = __floats2half2_rn(v.z, v.w);
        *(uint2*)&Ah[r * 136 + c4 * 4] = make_uint2(h2_to_u(h01), h2_to_u(h23));
    }
    __syncthreads();

    int wid = tid >> 5;
    int mi = wid >> 1;          // 0..3
    int nj = (wid & 1) * 2;     // 0 or 2

    wmma::fragment<wmma::accumulator, 16, 16, 16, float> acc[2];
    wmma::fill_fragment(acc[0], 0.f);
    wmma::fill_fragment(acc[1], 0.f);

    #pragma unroll
    for (int k = 0; k < 8; k++) {
        wmma::fragment<wmma::matrix_a, 16, 16, 16, __half, wmma::row_major> af;
        wmma::load_matrix_sync(af, &Ah[mi * 16 * 136 + k * 16], 136);
        #pragma unroll
        for (int t = 0; t < 2; t++) {
            wmma::fragment<wmma::matrix_b, 16, 16, 16, __half, wmma::row_major> bf;
            wmma::load_matrix_sync(bf, &Bh[k * 16 * 72 + (nj + t) * 16], 72);
            wmma::mma_sync(acc[t], af, bf, acc[t]);
        }
    }
    __syncthreads();   // Ah reads done; reuse as fp32 staging (same 17408 B)

    float* stage = (float*)Ah;   // 64 x 68 floats
    wmma::store_matrix_sync(&stage[mi * 16 * 68 + nj * 16], acc[0], 68,
                            wmma::mem_row_major);
    wmma::store_matrix_sync(&stage[mi * 16 * 68 + (nj + 1) * 16], acc[1], 68,
                            wmma::mem_row_major);
    __syncthreads();

    // Store h0h fp16 + zero g_h1
    #pragma unroll
    for (int i = tid; i < 64 * 16; i += 256) {
        int r = i >> 4, c4 = i & 15;
        int grow = row0 + r;
        if (grow < n) {
            float4 v = *(float4*)&stage[r * 68 + c4 * 4];
            __half2 h01 = __floats2half2_rn(v.x, v.y);
            __half2 h23 = __floats2half2_rn(v.z, v.w);
            *(uint2*)&g_h0h[grow * NH + c4 * 4] = make_uint2(h2_to_u(h01), h2_to_u(h23));
            *(float4*)&g_h1[grow * NH + c4 * 4] = make_float4(0.f, 0.f, 0.f, 0.f);
        }
    }
}

// ---------------------------------------------------------------------------
// Scatter1: g_h1[dst] += h0h[src] * w.  R14 geometry (160.3us run, at REDG floor):
// 64 edges/block, 16 lanes/edge, 4 edges/thread, lane: LDG.64 fp16 + 1 RED.v4.
// ---------------------------------------------------------------------------
__global__ void __launch_bounds__(256) scatter1_kernel(
    const int* __restrict__ ei, const float* __restrict__ ew, int E)
{
    __shared__ int   ssrc[64];
    __shared__ int   sdst[64];
    __shared__ float sw[64];

    int tid = threadIdx.x;
    int ebase = blockIdx.x * 64;
    if (tid < 64) {
        int e = ebase + tid;
        ssrc[tid] = (e < E) ? __ldg(&ei[e]) : -1;
    } else if (tid < 128) {
        int e = ebase + (tid - 64);
        sdst[tid - 64] = (e < E) ? __ldg(&ei[E + e]) : 0;
    } else if (tid < 192) {
        int e = ebase + (tid - 128);
        sw[tid - 128] = (e < E) ? __ldg(&ew[e]) : 0.f;
    }
    __syncthreads();

    int g = tid >> 4;          // edge-slot 0..15
    int q = tid & 15;          // feature quad 0..15

    int   s[4], d[4];
    float w[4];
    uint2 raw[4];

    #pragma unroll
    for (int u = 0; u < 4; u++) {
        int le = g + u * 16;
        s[u] = ssrc[le];
        d[u] = sdst[le];
        w[u] = sw[le];
    }
    #pragma unroll
    for (int u = 0; u < 4; u++) {
        raw[u] = make_uint2(0, 0);
        if (s[u] >= 0)
            raw[u] = __ldg((const uint2*)(g_h0h + s[u] * NH + q * 4));
    }
    #pragma unroll
    for (int u = 0; u < 4; u++) {
        if (s[u] >= 0) {
            float wt = w[u];
            float2 f0 = __half22float2(u_to_h2(raw[u].x));
            float2 f1 = __half22float2(u_to_h2(raw[u].y));
            asm volatile("red.global.add.v4.f32 [%0], {%1,%2,%3,%4};"
                         :: "l"(&g_h1[d[u] * NH + q * 4]),
                            "f"(f0.x * wt), "f"(f0.y * wt),
                            "f"(f1.x * wt), "f"(f1.y * wt)
                         : "memory");
        }
    }
}

// ---------------------------------------------------------------------------
// GEMM2: h2 = relu(h1) @ W2 (fp32 math), stored fp16; zeroes d_out rows.
// ---------------------------------------------------------------------------
__global__ void __launch_bounds__(256) gemm2_kernel(
    const float* __restrict__ W2, float* __restrict__ out, int n)
{
    __shared__ float ws[NH * NC];
    __shared__ float hs[64 * 65];

    int tid = threadIdx.x;
    #pragma unroll
    for (int i = tid; i < NH * NC / 4; i += 256)
        ((float4*)ws)[i] = ((const float4*)W2)[i];

    int row0 = blockIdx.x * 64;
    #pragma unroll
    for (int idx = tid; idx < 64 * 64; idx += 256) {
        int r = idx >> 6, k = idx & 63;
        int grow = row0 + r;
        float v = 0.f;
        if (grow < n) v = g_h1[grow * NH + k];
        hs[r * 65 + k] = fmaxf(v, 0.f);   // fused ReLU
    }
    __syncthreads();

    int cg = tid & 3, r = tid >> 2;
    float a0 = 0.f, a1 = 0.f, a2 = 0.f, a3 = 0.f;
    #pragma unroll
    for (int k = 0; k < NH; k++) {
        float a = hs[r * 65 + k];
        float4 b = *(const float4*)&ws[k * NC + cg * 4];
        a0 += a * b.x; a1 += a * b.y; a2 += a * b.z; a3 += a * b.w;
    }

    int grow = row0 + r;
    if (grow < n) {
        __half2 h01 = __floats2half2_rn(a0, a1);
        __half2 h23 = __floats2half2_rn(a2, a3);
        *(uint2*)&g_h2h[grow * NC + cg * 4] = make_uint2(h2_to_u(h01), h2_to_u(h23));
        *(float4*)&out[grow * NC + cg * 4]  = make_float4(0.f, 0.f, 0.f, 0.f);
    }
}

// ---------------------------------------------------------------------------
// Scatter2: out[dst] += h2h[src] * w.  R14 geometry (27.3us, at REDG floor):
// 256 edges/block, 4 lanes/edge, 4 edges/thread, LDG.64 fp16 + 1 RED.v4.
// ---------------------------------------------------------------------------
__global__ void __launch_bounds__(256) scatter2_kernel(
    const int* __restrict__ ei, const float* __restrict__ ew,
    float* __restrict__ out, int E)
{
    __shared__ int   ssrc[256];
    __shared__ int   sdst[256];
    __shared__ float sw[256];

    int tid = threadIdx.x;
    int ebase = blockIdx.x * 256;
    {
        int e = ebase + tid;
        ssrc[tid] = (e < E) ? __ldg(&ei[e]) : -1;
        sdst[tid] = (e < E) ? __ldg(&ei[E + e]) : 0;
        sw[tid]   = (e < E) ? __ldg(&ew[e]) : 0.f;
    }
    __syncthreads();

    int g = tid >> 2;          // edge-slot 0..63
    int q = tid & 3;           // feature quad 0..3

    int   s[4], d[4];
    float w[4];
    uint2 raw[4];

    #pragma unroll
    for (int u = 0; u < 4; u++) {
        int le = g + u * 64;
        s[u] = ssrc[le];
        d[u] = sdst[le];
        w[u] = sw[le];
    }
    #pragma unroll
    for (int u = 0; u < 4; u++) {
        raw[u] = make_uint2(0, 0);
        if (s[u] >= 0)
            raw[u] = __ldg((const uint2*)(g_h2h + s[u] * NC + q * 4));
    }
    #pragma unroll
    for (int u = 0; u < 4; u++) {
        if (s[u] >= 0) {
            float wt = w[u];
            float2 f0 = __half22float2(u_to_h2(raw[u].x));
            float2 f1 = __half22float2(u_to_h2(raw[u].y));
            asm volatile("red.global.add.v4.f32 [%0], {%1,%2,%3,%4};"
                         :: "l"(&out[d[u] * NC + q * 4]),
                            "f"(f0.x * wt), "f"(f0.y * wt),
                            "f"(f1.x * wt), "f"(f1.y * wt)
                         : "memory");
        }
    }
}

// ---------------------------------------------------------------------------
extern "C" void kernel_launch(void* const* d_in, const int* in_sizes, int n_in,
                              void* d_out, int out_size)
{
    const float* x   = (const float*)d_in[0];
    const int*   ei1 = (const int*)  d_in[1];
    const int*   ei2 = (const int*)  d_in[2];
    const float* ew1 = (const float*)d_in[3];
    const float* ew2 = (const float*)d_in[4];
    const float* W1  = (const float*)d_in[5];
    const float* W2  = (const float*)d_in[6];
    float* out = (float*)d_out;

    int n  = in_sizes[0] / NF;
    int E1 = in_sizes[3];
    int E2 = in_sizes[4];
    int nb = (n + 63) / 64;

    gemm1_kernel<<<nb, 256>>>(x, W1, n);                       // HMMA; writes h0h, zeroes g_h1
    scatter1_kernel<<<(E1 + 63) / 64, 256>>>(ei1, ew1, E1);
    gemm2_kernel<<<nb, 256>>>(W2, out, n);                     // writes h2h, zeroes out
    scatter2_kernel<<<(E2 + 255) / 256, 256>>>(ei2, ew2, out, E2);
}